// round 9
// baseline (speedup 1.0000x reference)
#include <cuda_runtime.h>
#include <cuda_bf16.h>
#include <math.h>
#include <cstdint>

// ---------------------------------------------------------------------------
// GGNN layer, GB300. Split-bf16 HMMA GEMMs + CSR gather aggregation.
// Refold: mx = (S·X)@(Wm@gk) + deg·(bm@gk) + b0   (msg GEMM eliminated)
//         mh = X@grk + b1 ;  out = z*X + (1-z)*tanh(xh + r*rh)
// Precision: A=Ah+Al, B=Bh+Bl (bf16); D = AhBh + AlBh + AhBl (fp32 acc)
// Graph-capture-safe: kernel launches only (no memset/symbol APIs).
// ---------------------------------------------------------------------------

#define D_DIM 128
#define MAXN  50048            // 391*128 tile padding
#define MBTOT (MAXN / 16)      // 3128
#define MAXE  1200128

__device__ float g_Wmg[D_DIM * 384];             // (W1@W2)@gk
__device__ float g_bmg[384];                     // (b1@W2+b2)@gk
__device__ float g_mx[MAXN * 3 * D_DIM];
__device__ float g_mh[MAXN * 3 * D_DIM];
__device__ float g_deg[MAXN];
__device__ int   g_cnt[MAXN];
__device__ int   g_ofs[MAXN + 1];
__device__ int   g_cur[MAXN];
__device__ int   g_adj[MAXE];
// A operands in mma-fragment order: [mb][ks][lane] -> {hi uint4, lo uint4}
__device__ uint4 g_XF[MBTOT * 8 * 32 * 2];
__device__ uint4 g_GF[MBTOT * 8 * 32 * 2];
// 6 weight tiles (mh x3, mx x3) [n][k] bf16 pairs (linear rows, 256B)
__device__ __align__(16) unsigned int g_BhW[6 * 8192];
__device__ __align__(16) unsigned int g_BlW[6 * 8192];
__device__ float g_biasAll[6 * 128];

// ---------------------------------------------------------------------------
__device__ __forceinline__ uint32_t smem_u32(const void* p) {
    uint32_t a;
    asm("{ .reg .u64 t; cvta.to.shared.u64 t, %1; cvt.u32.u64 %0, t; }"
        : "=r"(a) : "l"(p));
    return a;
}
__device__ __forceinline__ void split2(float2 v, uint32_t& hp, uint32_t& lp) {
    asm("cvt.rn.bf16x2.f32 %0, %1, %2;" : "=r"(hp) : "f"(v.y), "f"(v.x));
    float h0 = __uint_as_float(hp << 16);
    float h1 = __uint_as_float(hp & 0xFFFF0000u);
    asm("cvt.rn.bf16x2.f32 %0, %1, %2;" : "=r"(lp) : "f"(v.y - h1), "f"(v.x - h0));
}
__device__ __forceinline__ void ldsm4(uint32_t& r0, uint32_t& r1, uint32_t& r2,
                                      uint32_t& r3, uint32_t addr) {
    asm volatile("ldmatrix.sync.aligned.m8n8.x4.shared.b16 {%0,%1,%2,%3}, [%4];"
                 : "=r"(r0), "=r"(r1), "=r"(r2), "=r"(r3) : "r"(addr));
}
__device__ __forceinline__ void mma16816(float* c, const uint32_t* a,
                                         const uint32_t* b) {
    asm volatile(
        "mma.sync.aligned.m16n8k16.row.col.f32.bf16.bf16.f32 "
        "{%0,%1,%2,%3}, {%4,%5,%6,%7}, {%8,%9}, {%0,%1,%2,%3};"
        : "+f"(c[0]), "+f"(c[1]), "+f"(c[2]), "+f"(c[3])
        : "r"(a[0]), "r"(a[1]), "r"(a[2]), "r"(a[3]), "r"(b[0]), "r"(b[1]));
}
__device__ __forceinline__ void cpa16(uint32_t dst, const void* src) {
    asm volatile("cp.async.cg.shared.global [%0], [%1], 16;"
                 :: "r"(dst), "l"(src));
}

// ---------------------------------------------------------------------------
// weight folding:  Wmg = (W1@W2)@gk,  bmg = (b1@W2+b2)@gk
// ---------------------------------------------------------------------------
__global__ void __launch_bounds__(384) k_foldA(const float* __restrict__ W1,
                                               const float* __restrict__ W2,
                                               const float* __restrict__ gk) {
    __shared__ float w1r[128], wmr[128];
    int i = blockIdx.x, t = threadIdx.x;
    if (t < 128) w1r[t] = W1[i * 128 + t];
    __syncthreads();
    if (t < 128) {
        float s = 0.f;
#pragma unroll 8
        for (int k = 0; k < 128; k++) s += w1r[k] * W2[k * 128 + t];
        wmr[t] = s;
    }
    __syncthreads();
    float s = 0.f;
#pragma unroll 8
    for (int k = 0; k < 128; k++) s += wmr[k] * gk[k * 384 + t];
    g_Wmg[i * 384 + t] = s;
}

__global__ void __launch_bounds__(384) k_foldB(const float* __restrict__ b1,
                                               const float* __restrict__ W2,
                                               const float* __restrict__ b2,
                                               const float* __restrict__ gk) {
    __shared__ float bmr[128];
    int t = threadIdx.x;
    if (t < 128) {
        float s = b2[t];
        for (int k = 0; k < 128; k++) s += b1[k] * W2[k * 128 + t];
        bmr[t] = s;
    }
    __syncthreads();
    float s = 0.f;
#pragma unroll 8
    for (int k = 0; k < 128; k++) s += bmr[k] * gk[k * 384 + t];
    g_bmg[t] = s;
}

// split weight tiles [n][k] (hi/lo) + biases. j<3: grk (mh); j>=3: Wmg (mx).
__global__ void __launch_bounds__(256)
k_prepW(const float* __restrict__ grk, const float* __restrict__ gb) {
    int j = blockIdx.x, tid = threadIdx.x;
    int n = tid & 127, half = tid >> 7;
    const float* src = (j < 3) ? grk : g_Wmg;
    int c0 = (j % 3) * 128;
    const float* bsrc = gb + ((j < 3) ? 384 : 0) + c0;
    unsigned int* bh = g_BhW + (size_t)j * 8192 + n * 64;
    unsigned int* bl = g_BlW + (size_t)j * 8192 + n * 64;
    for (int k = half * 64; k < half * 64 + 64; k += 2) {
        float2 v = make_float2(src[(size_t)k * 384 + c0 + n],
                               src[(size_t)(k + 1) * 384 + c0 + n]);
        uint32_t hp, lp; split2(v, hp, lp);
        bh[k >> 1] = hp;
        bl[k >> 1] = lp;
    }
    if (half == 0) g_biasAll[j * 128 + n] = bsrc[n];
}

// ---------------------------------------------------------------------------
// CSR build (kernel-only; no memset APIs)
// ---------------------------------------------------------------------------
__global__ void k_zerocnt(int n) {
    int i = blockIdx.x * blockDim.x + threadIdx.x;
    if (i < n) g_cnt[i] = 0;
}

__global__ void k_hist(const int* __restrict__ ra, const int* __restrict__ rb,
                       int E) {
    int e = blockIdx.x * blockDim.x + threadIdx.x;
    if (e >= E) return;
    atomicAdd(&g_cnt[ra[e]], 1);
    atomicAdd(&g_cnt[rb[e]], 1);
}

__global__ void __launch_bounds__(1024) k_scan() {
    __shared__ int ssum[1024];
    const int C = 49;                       // 1024*49 >= MAXN
    int tid = threadIdx.x;
    int base = tid * C;
    int s = 0;
    for (int i = base; i < base + C && i < MAXN; i++) s += g_cnt[i];
    ssum[tid] = s;
    __syncthreads();
    for (int off = 1; off < 1024; off <<= 1) {
        int v = (tid >= off) ? ssum[tid - off] : 0;
        __syncthreads();
        ssum[tid] += v;
        __syncthreads();
    }
    int run = (tid > 0) ? ssum[tid - 1] : 0;
    for (int i = base; i < base + C && i < MAXN; i++) {
        int c = g_cnt[i];
        g_ofs[i] = run;
        g_cur[i] = run;
        g_deg[i] = (float)c;
        run += c;
    }
    if (tid == 1023) g_ofs[MAXN] = run;
}

__global__ void k_fill(const int* __restrict__ ra, const int* __restrict__ rb,
                       int E) {
    int e = blockIdx.x * blockDim.x + threadIdx.x;
    if (e >= E) return;
    int a = ra[e], b = rb[e];
    int pa = atomicAdd(&g_cur[a], 1);
    g_adj[pa] = b;
    int pb = atomicAdd(&g_cur[b], 1);
    g_adj[pb] = a;
}

// ---------------------------------------------------------------------------
// split X into fragment-major hi/lo (g_XF)
// ---------------------------------------------------------------------------
__global__ void __launch_bounds__(256)
k_split(const float* __restrict__ X, int N) {
    int mb = blockIdx.x;
    int ks = threadIdx.x >> 5, lane = threadIdx.x & 31;
    int r0 = mb * 16 + (lane >> 2), r1 = r0 + 8;
    int k0 = ks * 16 + (lane & 3) * 2;
    float2 z2 = make_float2(0.f, 0.f);
    float2 v00 = (r0 < N) ? *(const float2*)(X + (size_t)r0 * 128 + k0)     : z2;
    float2 v01 = (r0 < N) ? *(const float2*)(X + (size_t)r0 * 128 + k0 + 8) : z2;
    float2 v10 = (r1 < N) ? *(const float2*)(X + (size_t)r1 * 128 + k0)     : z2;
    float2 v11 = (r1 < N) ? *(const float2*)(X + (size_t)r1 * 128 + k0 + 8) : z2;
    uint32_t h0, l0, h1, l1, h2, l2, h3, l3;
    split2(v00, h0, l0);
    split2(v10, h1, l1);
    split2(v01, h2, l2);
    split2(v11, h3, l3);
    size_t f = ((size_t)(mb * 8 + ks) * 32 + lane) * 2;
    g_XF[f]     = make_uint4(h0, h1, h2, h3);
    g_XF[f + 1] = make_uint4(l0, l1, l2, l3);
}

// ---------------------------------------------------------------------------
// CSR gather: block = 16 nodes (one m-block). Warp w accumulates node's row
// into smem; phase 2 emits hi/lo fragments directly to g_GF (fused split).
// ---------------------------------------------------------------------------
__global__ void __launch_bounds__(512)
k_gather(const float* __restrict__ X) {
    __shared__ float rows[16][132];          // pad 132 to kill bank conflicts
    int mb = blockIdx.x;
    int tid = threadIdx.x, w = tid >> 5, lane = tid & 31;
    int node = mb * 16 + w;

    int s0 = g_ofs[node], e0 = g_ofs[node + 1];
    const float4* Xv = (const float4*)X;
    float4 acc = make_float4(0.f, 0.f, 0.f, 0.f);
    int p = s0;
    for (; p + 4 <= e0; p += 4) {
        int i0 = g_adj[p], i1 = g_adj[p + 1], i2 = g_adj[p + 2], i3 = g_adj[p + 3];
        float4 v0 = Xv[(size_t)i0 * 32 + lane];
        float4 v1 = Xv[(size_t)i1 * 32 + lane];
        float4 v2 = Xv[(size_t)i2 * 32 + lane];
        float4 v3 = Xv[(size_t)i3 * 32 + lane];
        acc.x += v0.x + v1.x + v2.x + v3.x;
        acc.y += v0.y + v1.y + v2.y + v3.y;
        acc.z += v0.z + v1.z + v2.z + v3.z;
        acc.w += v0.w + v1.w + v2.w + v3.w;
    }
    for (; p < e0; p++) {
        int i0 = g_adj[p];
        float4 v0 = Xv[(size_t)i0 * 32 + lane];
        acc.x += v0.x; acc.y += v0.y; acc.z += v0.z; acc.w += v0.w;
    }
    *(float4*)&rows[w][lane * 4] = acc;
    __syncthreads();

    if (tid < 256) {
        int ks = tid >> 5;
        int r0 = (tid & 31) >> 2, r1 = r0 + 8;
        int k0 = ks * 16 + (tid & 3) * 2;
        float2 v00 = *(const float2*)&rows[r0][k0];
        float2 v01 = *(const float2*)&rows[r0][k0 + 8];
        float2 v10 = *(const float2*)&rows[r1][k0];
        float2 v11 = *(const float2*)&rows[r1][k0 + 8];
        uint32_t h0, l0, h1, l1, h2, l2, h3, l3;
        split2(v00, h0, l0);
        split2(v10, h1, l1);
        split2(v01, h2, l2);
        split2(v11, h3, l3);
        size_t f = ((size_t)(mb * 8 + ks) * 32 + (tid & 31)) * 2;
        g_GF[f]     = make_uint4(h0, h1, h2, h3);
        g_GF[f + 1] = make_uint4(l0, l1, l2, l3);
    }
}

// ---------------------------------------------------------------------------
// persistent split-bf16 HMMA GEMM (barrier-free inner loop, B loaded once).
// jbase=0: mh (A=XF); jbase=3: mx (A=GF, bias += deg*bmg).
// ---------------------------------------------------------------------------
#define SM_TOTAL 65536

__global__ void __launch_bounds__(256, 2)
k_mmagemm(int useGF, int jbase, int mtiles) {
    extern __shared__ char smem[];
    const uint32_t sb = smem_u32(smem);
    const int tid = threadIdx.x, wid = tid >> 5, lane = tid & 31;
    const int j = jbase + blockIdx.y;

    {   // load B tile once
        int r = tid >> 1, h = tid & 1;
        const char* s = (const char*)(h ? g_BlW : g_BhW)
                        + (size_t)j * 32768 + (size_t)r * 256;
        uint32_t drow = sb + h * 32768 + r * 256;
        uint32_t rx = (uint32_t)(r & 7);
#pragma unroll
        for (int c = 0; c < 16; c++)
            cpa16(drow + (((uint32_t)c ^ rx) << 4), s + c * 16);
        asm volatile("cp.async.commit_group;" ::: "memory");
        asm volatile("cp.async.wait_group 0;" ::: "memory");
        __syncthreads();
    }

    const int warp_m = wid >> 1, warp_n = wid & 1;
    const int b_row = warp_n * 64 + (lane & 7) + ((lane >> 4) << 3);
    const uint32_t b_rx = (uint32_t)(b_row & 7);
    const int b_sel = (lane >> 3) & 1;
    const uint32_t bBaseHi = sb + b_row * 256;
    const uint32_t bBaseLo = bBaseHi + 32768;

    float* dst = (j < 3) ? g_mh : g_mx;
    const int c0 = (j % 3) * 128;
    const int useDeg = (jbase >= 3);
    const float* biasG = g_biasAll + j * 128;
    const float* bmgG  = g_bmg + c0;
    const int tr = lane >> 2, tc = (lane & 3) * 2;
    float bx[8], by[8], gx[8], gy[8];
#pragma unroll
    for (int nf = 0; nf < 8; nf++) {
        int col = warp_n * 64 + nf * 8 + tc;
        bx[nf] = biasG[col];
        by[nf] = biasG[col + 1];
        gx[nf] = useDeg ? bmgG[col]     : 0.f;
        gy[nf] = useDeg ? bmgG[col + 1] : 0.f;
    }

    const uint4* AF = useGF ? g_GF : g_XF;

    for (int mt = blockIdx.x; mt < mtiles; mt += gridDim.x) {
        float acc[2][8][4];
#pragma unroll
        for (int mf = 0; mf < 2; mf++)
#pragma unroll
            for (int nf = 0; nf < 8; nf++)
#pragma unroll
                for (int q = 0; q < 4; q++) acc[mf][nf][q] = 0.f;

        const int mbBase = mt * 8 + warp_m * 2;
        const uint4* a0 = AF + (((size_t)mbBase * 8) * 32 + lane) * 2;
        const uint4* a1 = AF + (((size_t)(mbBase + 1) * 8) * 32 + lane) * 2;

#pragma unroll
        for (int s = 0; s < 8; s++) {
            uint4 ahv0 = a0[s * 64], alv0 = a0[s * 64 + 1];
            uint4 ahv1 = a1[s * 64], alv1 = a1[s * 64 + 1];
            const uint32_t* ah0 = &ahv0.x;
            const uint32_t* al0 = &alv0.x;
            const uint32_t* ah1 = &ahv1.x;
            const uint32_t* al1 = &alv1.x;

            uint32_t bfr[16];
            uint32_t lc = (uint32_t)(2 * s + b_sel);
#pragma unroll
            for (int p = 0; p < 4; p++)
                ldsm4(bfr[p * 4], bfr[p * 4 + 1], bfr[p * 4 + 2], bfr[p * 4 + 3],
                      bBaseHi + p * 16 * 256 + ((lc ^ b_rx) << 4));
#pragma unroll
            for (int nf = 0; nf < 8; nf++) {
                const uint32_t* bs = &bfr[(nf >> 1) * 4 + (nf & 1) * 2];
                mma16816(acc[0][nf], ah0, bs);
                mma16816(acc[1][nf], ah1, bs);
                mma16816(acc[0][nf], al0, bs);
                mma16816(acc[1][nf], al1, bs);
            }
#pragma unroll
            for (int p = 0; p < 4; p++)
                ldsm4(bfr[p * 4], bfr[p * 4 + 1], bfr[p * 4 + 2], bfr[p * 4 + 3],
                      bBaseLo + p * 16 * 256 + ((lc ^ b_rx) << 4));
#pragma unroll
            for (int nf = 0; nf < 8; nf++) {
                const uint32_t* bs = &bfr[(nf >> 1) * 4 + (nf & 1) * 2];
                mma16816(acc[0][nf], ah0, bs);
                mma16816(acc[1][nf], ah1, bs);
            }
        }

        const int m0 = mt * 128;
#pragma unroll
        for (int mf = 0; mf < 2; mf++) {
            int row0 = m0 + warp_m * 32 + mf * 16 + tr;
            float dA = useDeg ? g_deg[row0]     : 0.f;
            float dB = useDeg ? g_deg[row0 + 8] : 0.f;
#pragma unroll
            for (int nf = 0; nf < 8; nf++) {
                int col = warp_n * 64 + nf * 8 + tc;
                *(float2*)(dst + (size_t)row0 * 384 + c0 + col) =
                    make_float2(acc[mf][nf][0] + bx[nf] + dA * gx[nf],
                                acc[mf][nf][1] + by[nf] + dA * gy[nf]);
                *(float2*)(dst + (size_t)(row0 + 8) * 384 + c0 + col) =
                    make_float2(acc[mf][nf][2] + bx[nf] + dB * gx[nf],
                                acc[mf][nf][3] + by[nf] + dB * gy[nf]);
            }
        }
    }
}

// ---------------------------------------------------------------------------
__device__ __forceinline__ float sgm(float x) { return 1.f / (1.f + expf(-x)); }

__global__ void __launch_bounds__(256) k_gru(const float* __restrict__ X,
                                             float* __restrict__ out, int n4) {
    int i = blockIdx.x * 256 + threadIdx.x;
    if (i >= n4) return;
    int node = i >> 5, c = i & 31;
    const float4* mx = (const float4*)g_mx + (size_t)node * 96;
    const float4* mh = (const float4*)g_mh + (size_t)node * 96;
    float4 xz = mx[c],      rz = mh[c];
    float4 xr = mx[32 + c], rr = mh[32 + c];
    float4 xh = mx[64 + c], rh = mh[64 + c];
    float4 x  = ((const float4*)X)[i];
    float4 o;
    { float z = sgm(xz.x + rz.x), r = sgm(xr.x + rr.x);
      o.x = z * x.x + (1.f - z) * tanhf(xh.x + r * rh.x); }
    { float z = sgm(xz.y + rz.y), r = sgm(xr.y + rr.y);
      o.y = z * x.y + (1.f - z) * tanhf(xh.y + r * rh.y); }
    { float z = sgm(xz.z + rz.z), r = sgm(xr.z + rr.z);
      o.z = z * x.z + (1.f - z) * tanhf(xh.z + r * rh.z); }
    { float z = sgm(xz.w + rz.w), r = sgm(xr.w + rr.w);
      o.w = z * x.w + (1.f - z) * tanhf(xh.w + r * rh.w); }
    ((float4*)out)[i] = o;
}

// ---------------------------------------------------------------------------
extern "C" void kernel_launch(void* const* d_in, const int* in_sizes, int n_in,
                              void* d_out, int out_size)
{
    const float* X   = (const float*)d_in[0];
    const int*   ra  = (const int*)  d_in[1];
    const int*   rb  = (const int*)  d_in[2];
    const float* W1  = (const float*)d_in[3];
    const float* b1  = (const float*)d_in[4];
    const float* W2  = (const float*)d_in[5];
    const float* b2  = (const float*)d_in[6];
    const float* gk  = (const float*)d_in[7];
    const float* grk = (const float*)d_in[8];
    const float* gb  = (const float*)d_in[9];

    const int N = in_sizes[0] / D_DIM;
    const int E = in_sizes[1];
    const int mtiles = (N + 127) / 128;          // 391
    const int mbtot  = mtiles * 8;               // 3128

    cudaFuncSetAttribute(k_mmagemm, cudaFuncAttributeMaxDynamicSharedMemorySize,
                         SM_TOTAL);

    // weight folding + split weight tiles
    k_foldA<<<128, 384>>>(W1, W2, gk);
    k_foldB<<<1, 384>>>(b1, W2, b2, gk);
    k_prepW<<<6, 256>>>(grk, gb);

    // CSR build (kernel-only zeroing; graph-capture safe)
    k_zerocnt<<<(MAXN + 255) / 256, 256>>>(MAXN);
    k_hist<<<(E + 255) / 256, 256>>>(ra, rb, E);
    k_scan<<<1, 1024>>>();
    k_fill<<<(E + 255) / 256, 256>>>(ra, rb, E);

    // split X + mh GEMM
    k_split<<<mbtot, 256>>>(X, N);
    k_mmagemm<<<dim3(98, 3), 256, SM_TOTAL>>>(0, 0, mtiles);

    // gather (fused agg-split) + mx GEMM
    k_gather<<<mbtot, 512>>>(X);
    k_mmagemm<<<dim3(98, 3), 256, SM_TOTAL>>>(1, 3, mtiles);

    // fused GRU update
    k_gru<<<(N * 32 + 255) / 256, 256>>>(X, (float*)d_out, N * 32);
}

// round 10
// speedup vs baseline: 1.1461x; 1.1461x over previous
#include <cuda_runtime.h>
#include <cuda_bf16.h>
#include <math.h>
#include <cstdint>

// ---------------------------------------------------------------------------
// GGNN layer, GB300. Split-bf16 HMMA GEMMs + fp32 atomic scatter of X.
// Refold: mx = (S·X)@(Wm@gk) + deg·(bm@gk) + b0   (msg GEMM eliminated)
//         mh = X@grk + b1 ;  out = z*X + (1-z)*tanh(xh + r*rh)
// Precision: A=Ah+Al, B=Bh+Bl (bf16); D = AhBh + AlBh + AhBl (fp32 acc)
// ---------------------------------------------------------------------------

#define D_DIM 128
#define MAXN  50048            // 391*128 tile padding
#define MBTOT (MAXN / 16)      // 3128

__device__ float g_Wmg[D_DIM * 384];             // (W1@W2)@gk
__device__ float g_bmg[384];                     // (b1@W2+b2)@gk
__device__ float g_agg[MAXN * D_DIM];            // S·X
__device__ float g_deg[MAXN];
__device__ float g_mx[MAXN * 3 * D_DIM];
__device__ float g_mh[MAXN * 3 * D_DIM];
// A operands in mma-fragment order: [mb][ks][lane] -> {hi uint4, lo uint4}
__device__ uint4 g_XF[MBTOT * 8 * 32 * 2];
__device__ uint4 g_GF[MBTOT * 8 * 32 * 2];
// 6 weight tiles (mh x3, mx x3) [n][k] bf16 pairs (linear rows, 256B)
__device__ __align__(16) unsigned int g_BhW[6 * 8192];
__device__ __align__(16) unsigned int g_BlW[6 * 8192];
__device__ float g_biasAll[6 * 128];

// ---------------------------------------------------------------------------
__device__ __forceinline__ uint32_t smem_u32(const void* p) {
    uint32_t a;
    asm("{ .reg .u64 t; cvta.to.shared.u64 t, %1; cvt.u32.u64 %0, t; }"
        : "=r"(a) : "l"(p));
    return a;
}
__device__ __forceinline__ void split2(float2 v, uint32_t& hp, uint32_t& lp) {
    asm("cvt.rn.bf16x2.f32 %0, %1, %2;" : "=r"(hp) : "f"(v.y), "f"(v.x));
    float h0 = __uint_as_float(hp << 16);
    float h1 = __uint_as_float(hp & 0xFFFF0000u);
    asm("cvt.rn.bf16x2.f32 %0, %1, %2;" : "=r"(lp) : "f"(v.y - h1), "f"(v.x - h0));
}
__device__ __forceinline__ void ldsm4(uint32_t& r0, uint32_t& r1, uint32_t& r2,
                                      uint32_t& r3, uint32_t addr) {
    asm volatile("ldmatrix.sync.aligned.m8n8.x4.shared.b16 {%0,%1,%2,%3}, [%4];"
                 : "=r"(r0), "=r"(r1), "=r"(r2), "=r"(r3) : "r"(addr));
}
__device__ __forceinline__ void mma16816(float* c, const uint32_t* a,
                                         const uint32_t* b) {
    asm volatile(
        "mma.sync.aligned.m16n8k16.row.col.f32.bf16.bf16.f32 "
        "{%0,%1,%2,%3}, {%4,%5,%6,%7}, {%8,%9}, {%0,%1,%2,%3};"
        : "+f"(c[0]), "+f"(c[1]), "+f"(c[2]), "+f"(c[3])
        : "r"(a[0]), "r"(a[1]), "r"(a[2]), "r"(a[3]), "r"(b[0]), "r"(b[1]));
}
__device__ __forceinline__ void cpa16(uint32_t dst, const void* src) {
    asm volatile("cp.async.cg.shared.global [%0], [%1], 16;"
                 :: "r"(dst), "l"(src));
}

// ---------------------------------------------------------------------------
// weight folding:  Wmg = (W1@W2)@gk,  bmg = (b1@W2+b2)@gk
// ---------------------------------------------------------------------------
__global__ void __launch_bounds__(384) k_foldA(const float* __restrict__ W1,
                                               const float* __restrict__ W2,
                                               const float* __restrict__ gk) {
    __shared__ float w1r[128], wmr[128];
    int i = blockIdx.x, t = threadIdx.x;
    if (t < 128) w1r[t] = W1[i * 128 + t];
    __syncthreads();
    if (t < 128) {
        float s = 0.f;
#pragma unroll 8
        for (int k = 0; k < 128; k++) s += w1r[k] * W2[k * 128 + t];
        wmr[t] = s;
    }
    __syncthreads();
    float s = 0.f;
#pragma unroll 8
    for (int k = 0; k < 128; k++) s += wmr[k] * gk[k * 384 + t];
    g_Wmg[i * 384 + t] = s;
}

__global__ void __launch_bounds__(384) k_foldB(const float* __restrict__ b1,
                                               const float* __restrict__ W2,
                                               const float* __restrict__ b2,
                                               const float* __restrict__ gk) {
    __shared__ float bmr[128];
    int t = threadIdx.x;
    if (t < 128) {
        float s = b2[t];
        for (int k = 0; k < 128; k++) s += b1[k] * W2[k * 128 + t];
        bmr[t] = s;
    }
    __syncthreads();
    float s = 0.f;
#pragma unroll 8
    for (int k = 0; k < 128; k++) s += bmr[k] * gk[k * 384 + t];
    g_bmg[t] = s;
}

// split weight tiles [n][k] (hi/lo) + biases. j<3: grk (mh); j>=3: Wmg (mx).
__global__ void __launch_bounds__(256)
k_prepW(const float* __restrict__ grk, const float* __restrict__ gb) {
    int j = blockIdx.x, tid = threadIdx.x;
    int n = tid & 127, half = tid >> 7;
    const float* src = (j < 3) ? grk : g_Wmg;
    int c0 = (j % 3) * 128;
    const float* bsrc = gb + ((j < 3) ? 384 : 0) + c0;
    unsigned int* bh = g_BhW + (size_t)j * 8192 + n * 64;
    unsigned int* bl = g_BlW + (size_t)j * 8192 + n * 64;
    for (int k = half * 64; k < half * 64 + 64; k += 2) {
        float2 v = make_float2(src[(size_t)k * 384 + c0 + n],
                               src[(size_t)(k + 1) * 384 + c0 + n]);
        uint32_t hp, lp; split2(v, hp, lp);
        bh[k >> 1] = hp;
        bl[k >> 1] = lp;
    }
    if (half == 0) g_biasAll[j * 128 + n] = bsrc[n];
}

// ---------------------------------------------------------------------------
// zero agg + deg
// ---------------------------------------------------------------------------
__global__ void k_zero(int n4) {
    int i = blockIdx.x * blockDim.x + threadIdx.x;
    if (i < n4) ((float4*)g_agg)[i] = make_float4(0.f, 0.f, 0.f, 0.f);
    if (i < MAXN / 4) ((float4*)g_deg)[i] = make_float4(0.f, 0.f, 0.f, 0.f);
}

// ---------------------------------------------------------------------------
// undirected scatter-add of X rows: warp per edge, red.v4 both directions.
// deg accumulated via scalar red.add on lanes 0/1.
// ---------------------------------------------------------------------------
__global__ void __launch_bounds__(256)
k_scatter(const float* __restrict__ X, const int* __restrict__ ra,
          const int* __restrict__ rb, int E) {
    int w    = (blockIdx.x * 256 + threadIdx.x) >> 5;
    int lane = threadIdx.x & 31;
    if (w >= E) return;
    int a = ra[w];
    int b = rb[w];
    float4 va = ((const float4*)(X + (size_t)a * 128))[lane];
    float4 vb = ((const float4*)(X + (size_t)b * 128))[lane];
    float* pb = g_agg + (size_t)b * 128 + lane * 4;
    float* pa = g_agg + (size_t)a * 128 + lane * 4;
    asm volatile("red.global.add.v4.f32 [%0], {%1,%2,%3,%4};"
                 :: "l"(pb), "f"(va.x), "f"(va.y), "f"(va.z), "f"(va.w) : "memory");
    asm volatile("red.global.add.v4.f32 [%0], {%1,%2,%3,%4};"
                 :: "l"(pa), "f"(vb.x), "f"(vb.y), "f"(vb.z), "f"(vb.w) : "memory");
    if (lane == 0)
        asm volatile("red.global.add.f32 [%0], %1;"
                     :: "l"(g_deg + b), "f"(1.0f) : "memory");
    if (lane == 1)
        asm volatile("red.global.add.f32 [%0], %1;"
                     :: "l"(g_deg + a), "f"(1.0f) : "memory");
}

// ---------------------------------------------------------------------------
// split X into fragment-major hi/lo (g_XF)
// ---------------------------------------------------------------------------
__global__ void __launch_bounds__(256)
k_split(const float* __restrict__ X, int N) {
    int mb = blockIdx.x;
    int ks = threadIdx.x >> 5, lane = threadIdx.x & 31;
    int r0 = mb * 16 + (lane >> 2), r1 = r0 + 8;
    int k0 = ks * 16 + (lane & 3) * 2;
    float2 z2 = make_float2(0.f, 0.f);
    float2 v00 = (r0 < N) ? *(const float2*)(X + (size_t)r0 * 128 + k0)     : z2;
    float2 v01 = (r0 < N) ? *(const float2*)(X + (size_t)r0 * 128 + k0 + 8) : z2;
    float2 v10 = (r1 < N) ? *(const float2*)(X + (size_t)r1 * 128 + k0)     : z2;
    float2 v11 = (r1 < N) ? *(const float2*)(X + (size_t)r1 * 128 + k0 + 8) : z2;
    uint32_t h0, l0, h1, l1, h2, l2, h3, l3;
    split2(v00, h0, l0);
    split2(v10, h1, l1);
    split2(v01, h2, l2);
    split2(v11, h3, l3);
    size_t f = ((size_t)(mb * 8 + ks) * 32 + lane) * 2;
    g_XF[f]     = make_uint4(h0, h1, h2, h3);
    g_XF[f + 1] = make_uint4(l0, l1, l2, l3);
}

// split agg into fragment-major hi/lo (g_GF); agg is zero-padded, no guards
__global__ void __launch_bounds__(256)
k_splitAgg(int N) {
    int mb = blockIdx.x;
    int ks = threadIdx.x >> 5, lane = threadIdx.x & 31;
    int r0 = mb * 16 + (lane >> 2), r1 = r0 + 8;
    int k0 = ks * 16 + (lane & 3) * 2;
    const float* A = g_agg;
    float2 v00 = *(const float2*)(A + (size_t)r0 * 128 + k0);
    float2 v01 = *(const float2*)(A + (size_t)r0 * 128 + k0 + 8);
    float2 v10 = *(const float2*)(A + (size_t)r1 * 128 + k0);
    float2 v11 = *(const float2*)(A + (size_t)r1 * 128 + k0 + 8);
    uint32_t h0, l0, h1, l1, h2, l2, h3, l3;
    split2(v00, h0, l0);
    split2(v10, h1, l1);
    split2(v01, h2, l2);
    split2(v11, h3, l3);
    size_t f = ((size_t)(mb * 8 + ks) * 32 + lane) * 2;
    g_GF[f]     = make_uint4(h0, h1, h2, h3);
    g_GF[f + 1] = make_uint4(l0, l1, l2, l3);
}

// ---------------------------------------------------------------------------
// persistent split-bf16 HMMA GEMM (barrier-free inner loop, B loaded once).
// jbase=0: mh (A=XF); jbase=3: mx (A=GF, bias += deg*bmg).
// ---------------------------------------------------------------------------
#define SM_TOTAL 65536

__global__ void __launch_bounds__(256, 2)
k_mmagemm(int useGF, int jbase, int mtiles) {
    extern __shared__ char smem[];
    const uint32_t sb = smem_u32(smem);
    const int tid = threadIdx.x, wid = tid >> 5, lane = tid & 31;
    const int j = jbase + blockIdx.y;

    {   // load B tile once
        int r = tid >> 1, h = tid & 1;
        const char* s = (const char*)(h ? g_BlW : g_BhW)
                        + (size_t)j * 32768 + (size_t)r * 256;
        uint32_t drow = sb + h * 32768 + r * 256;
        uint32_t rx = (uint32_t)(r & 7);
#pragma unroll
        for (int c = 0; c < 16; c++)
            cpa16(drow + (((uint32_t)c ^ rx) << 4), s + c * 16);
        asm volatile("cp.async.commit_group;" ::: "memory");
        asm volatile("cp.async.wait_group 0;" ::: "memory");
        __syncthreads();
    }

    const int warp_m = wid >> 1, warp_n = wid & 1;
    const int b_row = warp_n * 64 + (lane & 7) + ((lane >> 4) << 3);
    const uint32_t b_rx = (uint32_t)(b_row & 7);
    const int b_sel = (lane >> 3) & 1;
    const uint32_t bBaseHi = sb + b_row * 256;
    const uint32_t bBaseLo = bBaseHi + 32768;

    float* dst = (j < 3) ? g_mh : g_mx;
    const int c0 = (j % 3) * 128;
    const int useDeg = (jbase >= 3);
    const float* biasG = g_biasAll + j * 128;
    const float* bmgG  = g_bmg + c0;
    const int tr = lane >> 2, tc = (lane & 3) * 2;
    float bx[8], by[8], gx[8], gy[8];
#pragma unroll
    for (int nf = 0; nf < 8; nf++) {
        int col = warp_n * 64 + nf * 8 + tc;
        bx[nf] = biasG[col];
        by[nf] = biasG[col + 1];
        gx[nf] = useDeg ? bmgG[col]     : 0.f;
        gy[nf] = useDeg ? bmgG[col + 1] : 0.f;
    }

    const uint4* AF = useGF ? g_GF : g_XF;

    for (int mt = blockIdx.x; mt < mtiles; mt += gridDim.x) {
        float acc[2][8][4];
#pragma unroll
        for (int mf = 0; mf < 2; mf++)
#pragma unroll
            for (int nf = 0; nf < 8; nf++)
#pragma unroll
                for (int q = 0; q < 4; q++) acc[mf][nf][q] = 0.f;

        const int mbBase = mt * 8 + warp_m * 2;
        const uint4* a0 = AF + (((size_t)mbBase * 8) * 32 + lane) * 2;
        const uint4* a1 = AF + (((size_t)(mbBase + 1) * 8) * 32 + lane) * 2;

#pragma unroll
        for (int s = 0; s < 8; s++) {
            uint4 ahv0 = a0[s * 64], alv0 = a0[s * 64 + 1];
            uint4 ahv1 = a1[s * 64], alv1 = a1[s * 64 + 1];
            const uint32_t* ah0 = &ahv0.x;
            const uint32_t* al0 = &alv0.x;
            const uint32_t* ah1 = &ahv1.x;
            const uint32_t* al1 = &alv1.x;

            uint32_t bfr[16];
            uint32_t lc = (uint32_t)(2 * s + b_sel);
#pragma unroll
            for (int p = 0; p < 4; p++)
                ldsm4(bfr[p * 4], bfr[p * 4 + 1], bfr[p * 4 + 2], bfr[p * 4 + 3],
                      bBaseHi + p * 16 * 256 + ((lc ^ b_rx) << 4));
#pragma unroll
            for (int nf = 0; nf < 8; nf++) {
                const uint32_t* bs = &bfr[(nf >> 1) * 4 + (nf & 1) * 2];
                mma16816(acc[0][nf], ah0, bs);
                mma16816(acc[1][nf], ah1, bs);
                mma16816(acc[0][nf], al0, bs);
                mma16816(acc[1][nf], al1, bs);
            }
#pragma unroll
            for (int p = 0; p < 4; p++)
                ldsm4(bfr[p * 4], bfr[p * 4 + 1], bfr[p * 4 + 2], bfr[p * 4 + 3],
                      bBaseLo + p * 16 * 256 + ((lc ^ b_rx) << 4));
#pragma unroll
            for (int nf = 0; nf < 8; nf++) {
                const uint32_t* bs = &bfr[(nf >> 1) * 4 + (nf & 1) * 2];
                mma16816(acc[0][nf], ah0, bs);
                mma16816(acc[1][nf], ah1, bs);
            }
        }

        const int m0 = mt * 128;
#pragma unroll
        for (int mf = 0; mf < 2; mf++) {
            int row0 = m0 + warp_m * 32 + mf * 16 + tr;
            float dA = useDeg ? g_deg[row0]     : 0.f;
            float dB = useDeg ? g_deg[row0 + 8] : 0.f;
#pragma unroll
            for (int nf = 0; nf < 8; nf++) {
                int col = warp_n * 64 + nf * 8 + tc;
                *(float2*)(dst + (size_t)row0 * 384 + c0 + col) =
                    make_float2(acc[mf][nf][0] + bx[nf] + dA * gx[nf],
                                acc[mf][nf][1] + by[nf] + dA * gy[nf]);
                *(float2*)(dst + (size_t)(row0 + 8) * 384 + c0 + col) =
                    make_float2(acc[mf][nf][2] + bx[nf] + dB * gx[nf],
                                acc[mf][nf][3] + by[nf] + dB * gy[nf]);
            }
        }
    }
}

// ---------------------------------------------------------------------------
__device__ __forceinline__ float sgm(float x) { return 1.f / (1.f + expf(-x)); }

__global__ void __launch_bounds__(256) k_gru(const float* __restrict__ X,
                                             float* __restrict__ out, int n4) {
    int i = blockIdx.x * 256 + threadIdx.x;
    if (i >= n4) return;
    int node = i >> 5, c = i & 31;
    const float4* mx = (const float4*)g_mx + (size_t)node * 96;
    const float4* mh = (const float4*)g_mh + (size_t)node * 96;
    float4 xz = mx[c],      rz = mh[c];
    float4 xr = mx[32 + c], rr = mh[32 + c];
    float4 xh = mx[64 + c], rh = mh[64 + c];
    float4 x  = ((const float4*)X)[i];
    float4 o;
    { float z = sgm(xz.x + rz.x), r = sgm(xr.x + rr.x);
      o.x = z * x.x + (1.f - z) * tanhf(xh.x + r * rh.x); }
    { float z = sgm(xz.y + rz.y), r = sgm(xr.y + rr.y);
      o.y = z * x.y + (1.f - z) * tanhf(xh.y + r * rh.y); }
    { float z = sgm(xz.z + rz.z), r = sgm(xr.z + rr.z);
      o.z = z * x.z + (1.f - z) * tanhf(xh.z + r * rh.z); }
    { float z = sgm(xz.w + rz.w), r = sgm(xr.w + rr.w);
      o.w = z * x.w + (1.f - z) * tanhf(xh.w + r * rh.w); }
    ((float4*)out)[i] = o;
}

// ---------------------------------------------------------------------------
extern "C" void kernel_launch(void* const* d_in, const int* in_sizes, int n_in,
                              void* d_out, int out_size)
{
    const float* X   = (const float*)d_in[0];
    const int*   ra  = (const int*)  d_in[1];
    const int*   rb  = (const int*)  d_in[2];
    const float* W1  = (const float*)d_in[3];
    const float* b1  = (const float*)d_in[4];
    const float* W2  = (const float*)d_in[5];
    const float* b2  = (const float*)d_in[6];
    const float* gk  = (const float*)d_in[7];
    const float* grk = (const float*)d_in[8];
    const float* gb  = (const float*)d_in[9];

    const int N = in_sizes[0] / D_DIM;
    const int E = in_sizes[1];
    const int mtiles = (N + 127) / 128;          // 391
    const int mbtot  = mtiles * 8;               // 3128

    cudaFuncSetAttribute(k_mmagemm, cudaFuncAttributeMaxDynamicSharedMemorySize,
                         SM_TOTAL);

    // 1-3: weight folding + split weight tiles
    k_foldA<<<128, 384>>>(W1, W2, gk);
    k_foldB<<<1, 384>>>(b1, W2, b2, gk);
    k_prepW<<<6, 256>>>(grk, gb);

    // 4-5: zero agg+deg, split X
    k_zero<<<(MAXN * 32 + 255) / 256, 256>>>(MAXN * 32);
    k_split<<<mbtot, 256>>>(X, N);

    // 6 (profiled): undirected scatter of X rows + degree
    k_scatter<<<(E + 7) / 8, 256>>>(X, ra, rb, E);

    // 7: mh GEMM (A = XF)
    k_mmagemm<<<dim3(98, 3), 256, SM_TOTAL>>>(0, 0, mtiles);

    // 8-9: split agg, mx GEMM (A = GF, deg-scaled bias)
    k_splitAgg<<<mbtot, 256>>>(N);
    k_mmagemm<<<dim3(98, 3), 256, SM_TOTAL>>>(1, 3, mtiles);

    // 10: fused GRU update
    k_gru<<<(N * 32 + 255) / 256, 256>>>(X, (float*)d_out, N * 32);
}